// round 2
// baseline (speedup 1.0000x reference)
#include <cuda_runtime.h>
#include <cuda_bf16.h>
#include <cstdint>

// Cross-stitch: per-channel 2x2 mix.
//   out_a[n,c,h,w] = w[c,0,0]*x_a + w[c,0,1]*x_b
//   out_b[n,c,h,w] = w[c,1,0]*x_a + w[c,1,1]*x_b
// Shapes: x_a, x_b: [32, 256, 64, 64] fp32. weights: [256, 2, 2] fp32.
// Output: out_a followed by out_b.

static constexpr int C_ = 256;
static constexpr long long TOT  = 32LL * 256 * 64 * 64;   // 33,554,432 floats
static constexpr long long TOT4 = TOT / 4;                // 8,388,608 float4
static constexpr long long HALF4 = TOT4 / 2;              // 4,194,304 — multiple of 256 channel-rows
                                                          // so i4 and i4+HALF4 share the same channel

__global__ __launch_bounds__(256)
void cross_stitch_kernel(const float4* __restrict__ xa,
                         const float4* __restrict__ xb,
                         const float*  __restrict__ w,   // [C,2,2]
                         float4* __restrict__ oa,
                         float4* __restrict__ ob)
{
    long long i4 = (long long)blockIdx.x * blockDim.x + threadIdx.x;
    long long j4 = i4 + HALF4;

    // channel of float index (i4*4): (i4 >> 10) & 255. Same for j4 (HALF4 is a
    // multiple of 256 * 1024 float4s).
    int c = (int)((i4 >> 10) & (C_ - 1));
    const float* wc = w + c * 4;
    float w00 = __ldg(wc + 0);
    float w01 = __ldg(wc + 1);
    float w10 = __ldg(wc + 2);
    float w11 = __ldg(wc + 3);

    // Front-batched streaming loads (evict-first: no reuse, keep L2 clean).
    float4 a0 = __ldcs(xa + i4);
    float4 b0 = __ldcs(xb + i4);
    float4 a1 = __ldcs(xa + j4);
    float4 b1 = __ldcs(xb + j4);

    float4 ra0, rb0, ra1, rb1;
    ra0.x = fmaf(w00, a0.x, w01 * b0.x);
    ra0.y = fmaf(w00, a0.y, w01 * b0.y);
    ra0.z = fmaf(w00, a0.z, w01 * b0.z);
    ra0.w = fmaf(w00, a0.w, w01 * b0.w);
    rb0.x = fmaf(w10, a0.x, w11 * b0.x);
    rb0.y = fmaf(w10, a0.y, w11 * b0.y);
    rb0.z = fmaf(w10, a0.z, w11 * b0.z);
    rb0.w = fmaf(w10, a0.w, w11 * b0.w);

    ra1.x = fmaf(w00, a1.x, w01 * b1.x);
    ra1.y = fmaf(w00, a1.y, w01 * b1.y);
    ra1.z = fmaf(w00, a1.z, w01 * b1.z);
    ra1.w = fmaf(w00, a1.w, w01 * b1.w);
    rb1.x = fmaf(w10, a1.x, w11 * b1.x);
    rb1.y = fmaf(w10, a1.y, w11 * b1.y);
    rb1.z = fmaf(w10, a1.z, w11 * b1.z);
    rb1.w = fmaf(w10, a1.w, w11 * b1.w);

    // Streaming stores.
    __stcs(oa + i4, ra0);
    __stcs(ob + i4, rb0);
    __stcs(oa + j4, ra1);
    __stcs(ob + j4, rb1);
}

extern "C" void kernel_launch(void* const* d_in, const int* in_sizes, int n_in,
                              void* d_out, int out_size)
{
    const float4* xa = (const float4*)d_in[0];
    const float4* xb = (const float4*)d_in[1];
    const float*  w  = (const float*)d_in[2];

    float4* oa = (float4*)d_out;
    float4* ob = oa + TOT4;   // out_b follows out_a

    int threads = 256;
    long long blocks = HALF4 / threads;   // 16384
    cross_stitch_kernel<<<(unsigned)blocks, threads>>>(xa, xb, w, oa, ob);
}